// round 11
// baseline (speedup 1.0000x reference)
#include <cuda_runtime.h>

#define SIG_LEN  16777216
#define HOP      256
#define PAD      768
#define N_FRAMES 65539
#define N_ROWS   65542
#define HALF     513

// ---------------- compile-time tables (correctly-rounded, double precision) ----------------
constexpr double PI_D = 3.141592653589793238462643383279502884;

constexpr double tcos(double x) {
    double x2 = x * x, term = 1.0, s = 1.0;
    for (int i = 1; i <= 10; i++) { term *= -x2 / ((2.0 * i - 1.0) * (2.0 * i)); s += term; }
    return s;
}
constexpr double tsin(double x) {
    double x2 = x * x, term = x, s = x;
    for (int i = 1; i <= 10; i++) { term *= -x2 / ((2.0 * i) * (2.0 * i + 1.0)); s += term; }
    return s;
}
constexpr double cpi(double t) {
    while (t >= 2.0) t -= 2.0;
    while (t < 0.0) t += 2.0;
    if (t > 1.0) t = 2.0 - t;
    double sg = 1.0;
    if (t > 0.5) { t = 1.0 - t; sg = -1.0; }
    return sg * (t <= 0.25 ? tcos(PI_D * t) : tsin(PI_D * (0.5 - t)));
}
constexpr double spi(double t) {
    while (t >= 2.0) t -= 2.0;
    while (t < 0.0) t += 2.0;
    double sg = 1.0;
    if (t > 1.0) { t -= 1.0; sg = -1.0; }
    if (t > 0.5) t = 1.0 - t;
    return sg * (t <= 0.25 ? tsin(PI_D * t) : tcos(PI_D * (0.5 - t)));
}

struct Tables {
    float2 tw512[512];    // e^{-2pi i k/512}
    float2 tw64[64];      // {c,s} e^{-2pi i n0 j2/64}
    float2 tw1024[513];   // {c,s} e^{-i pi k/512}
    float2 win[512];      // (w[2n], w[2n+1]) / 32
};
constexpr Tables mk_tables() {
    Tables T{};
    for (int k = 0; k < 512; k++)
        T.tw512[k] = float2{ (float)cpi(k / 256.0), (float)(-spi(k / 256.0)) };
    for (int j2 = 0; j2 < 8; j2++)
        for (int n0 = 0; n0 < 8; n0++)
            T.tw64[j2 * 8 + n0] = float2{ (float)cpi(n0 * j2 / 32.0),
                                          (float)(-spi(n0 * j2 / 32.0)) };
    for (int k = 0; k <= 512; k++)
        T.tw1024[k] = float2{ (float)cpi(k / 512.0), (float)(-spi(k / 512.0)) };
    for (int n = 0; n < 512; n++)
        T.win[n] = float2{ (float)((0.54 - 0.46 * cpi(2.0 * (2 * n) / 1023.0)) / 32.0),
                           (float)((0.54 - 0.46 * cpi(2.0 * (2 * n + 1) / 1023.0)) / 32.0) };
    return T;
}
__device__ constexpr Tables TAB = mk_tables();

// ---------------- f32x2 packed primitives (2 frames in the 2 lanes) ----------------
typedef unsigned long long u64;

__device__ __forceinline__ u64 pk(float lo, float hi) {
    u64 r; asm("mov.b64 %0, {%1, %2};" : "=l"(r) : "f"(lo), "f"(hi)); return r;
}
__device__ __forceinline__ void upk(float& lo, float& hi, u64 v) {
    asm("mov.b64 {%0, %1}, %2;" : "=f"(lo), "=f"(hi) : "l"(v));
}
__device__ __forceinline__ u64 vadd(u64 a, u64 b) {
    u64 r; asm("add.rn.f32x2 %0, %1, %2;" : "=l"(r) : "l"(a), "l"(b)); return r;
}
__device__ __forceinline__ u64 vmul(u64 a, u64 b) {
    u64 r; asm("mul.rn.f32x2 %0, %1, %2;" : "=l"(r) : "l"(a), "l"(b)); return r;
}
__device__ __forceinline__ u64 vfma(u64 a, u64 b, u64 c) {
    u64 r; asm("fma.rn.f32x2 %0, %1, %2, %3;" : "=l"(r) : "l"(a), "l"(b), "l"(c)); return r;
}
__device__ __forceinline__ u64 vneg1() { return pk(-1.0f, -1.0f); }
__device__ __forceinline__ u64 vsub(u64 a, u64 b) { return vfma(b, vneg1(), a); }  // exact a-b

struct cp { u64 re, im; };
__device__ __forceinline__ cp cadd(cp a, cp b)   { return { vadd(a.re, b.re), vadd(a.im, b.im) }; }
__device__ __forceinline__ cp csub(cp a, cp b)   { return { vsub(a.re, b.re), vsub(a.im, b.im) }; }
// a + (-i)b = (are+bim, aim-bre);  a - (-i)b = (are-bim, aim+bre)
__device__ __forceinline__ cp caddmi(cp a, cp b) { return { vadd(a.re, b.im), vsub(a.im, b.re) }; }
__device__ __forceinline__ cp csubmi(cp a, cp b) { return { vsub(a.re, b.im), vadd(a.im, b.re) }; }
__device__ __forceinline__ cp cpmul(cp a, cp b) {
    cp r;
    r.re = vsub(vmul(a.re, b.re), vmul(a.im, b.im));
    r.im = vfma(a.re, b.im, vmul(a.im, b.re));
    return r;
}

__device__ __forceinline__ float fsqrt_fast(float x) {
    float r; asm("sqrt.approx.f32 %0, %1;" : "=f"(r) : "f"(x)); return r;
}

// Half-angle atan2 PAIR, reusing r = |X| (already computed for magnitude).
//   x >= 0: theta = 2*atan(y/(r+|x|));  x < 0: theta = sign(y)*pi - 2*atan(y/(r+|x|))
// 6-coeff odd minimax for atan on [-1,1] (abs err ~1e-5 rad), evaluated PACKED
// for the two bins. Sign via (y<0) comparison: y==-0.0 & x<0 -> +pi (matches
// reference at the Nyquist bin where our pair formula yields Im = -0.0).
__device__ __forceinline__ void fatan2_half2(float y0, float x0, float r0,
                                             float y1, float x1, float r1,
                                             float& th0, float& th1) {
    const float PI = 3.14159265358979323f;
    float den0 = r0 + fabsf(x0), den1 = r1 + fabsf(x1);
    float t0 = __fdividef(y0, den0); t0 = (den0 == 0.0f) ? 0.0f : t0;
    float t1 = __fdividef(y1, den1); t1 = (den1 == 0.0f) ? 0.0f : t1;
    u64 T = pk(t0, t1);
    u64 S = vmul(T, T);
    u64 P = vfma(vfma(vfma(vfma(vfma(pk(-0.02344240f, -0.02344240f), S,
                pk(0.10530664f, 0.10530664f)), S,
                pk(-0.23286574f, -0.23286574f)), S,
                pk(0.38708692f, 0.38708692f)), S,
                pk(-0.66524694f, -0.66524694f)), S,
                pk(1.99995452f, 1.99995452f));
    u64 TH = vmul(T, P);
    float a0, a1; upk(a0, a1, TH);
    th0 = (x0 < 0.0f) ? (((y0 < 0.0f) ? -PI : PI) - a0) : a0;
    th1 = (x1 < 0.0f) ? (((y1 < 0.0f) ? -PI : PI) - a1) : a1;
}

// scalar version for the center bin
__device__ __forceinline__ float fatan2_half(float y, float x, float r) {
    const float PI = 3.14159265358979323f;
    float den = r + fabsf(x);
    float t = __fdividef(y, den);
    t = (den == 0.0f) ? 0.0f : t;
    float s = t * t;
    float p = fmaf(fmaf(fmaf(fmaf(fmaf(-0.02344240f, s, 0.10530664f), s,
                 -0.23286574f), s, 0.38708692f), s, -0.66524694f), s, 1.99995452f);
    float th = t * p;
    if (x < 0.0f) th = ((y < 0.0f) ? -PI : PI) - th;
    return th;
}

// packed 8-point DFT (both frames simultaneously)
__device__ __forceinline__ void fft8p(cp* a) {
    const float Cf = 0.70710678118654752440f;
    u64 Cd = pk(Cf, Cf), nCd = pk(-Cf, -Cf);
    cp s0 = cadd(a[0], a[4]), s1 = csub(a[0], a[4]);
    cp s2 = cadd(a[2], a[6]), s3 = csub(a[2], a[6]);
    cp t0 = cadd(a[1], a[5]), t1 = csub(a[1], a[5]);
    cp t2 = cadd(a[3], a[7]), t3 = csub(a[3], a[7]);
    cp E0 = cadd(s0, s2), E2 = csub(s0, s2);
    cp E1 = caddmi(s1, s3), E3 = csubmi(s1, s3);
    cp O0 = cadd(t0, t2), O2 = csub(t0, t2);
    cp O1 = caddmi(t1, t3), O3 = csubmi(t1, t3);
    cp W1 = { vmul(vadd(O1.re, O1.im), Cd), vmul(vsub(O1.im, O1.re), Cd) };
    cp W3 = { vmul(vsub(O3.im, O3.re), Cd), vmul(vadd(O3.re, O3.im), nCd) };
    a[0] = cadd(E0, O0);   a[4] = csub(E0, O0);
    a[1] = cadd(E1, W1);   a[5] = csub(E1, W1);
    a[2] = caddmi(E2, O2); a[6] = csubmi(E2, O2);   // W2 = -i*O2 folded
    a[3] = cadd(E3, W3);   a[7] = csub(E3, W3);
}

// ---------------- fused STFT kernel: 128 threads, 2 frame-pairs (4 frames)/block ----------
// R9 skeleton (batched xs[10] loads = MLP 10, launch_bounds(128,8)) + dedup tables
// + packed atan2 pair.
__global__ __launch_bounds__(128, 8) void stft_kernel(const float* __restrict__ x,
                                                      float* __restrict__ out) {
    __shared__ ulonglong2 sA[2][512];

    const int t  = threadIdx.x;
    const int pr = t >> 6;            // frame-pair slot (0-1)
    const int tl = t & 63;
    const int f0 = blockIdx.x * 4 + pr * 2;   // lane .x frame
    const int f1 = f0 + 1;                    // lane .y frame
    const int st0 = f0 * HOP - PAD;
    const int hi = tl >> 3, lo = tl & 7;

    cp v[8];

    // ---- load (batched, shared across lanes: frame1 sample n == frame0 sample
    //      n+128, i.e. index m+2 here) + window ----
    float2 xs[10];
    const bool inb = (st0 >= 0) && (st0 + 2 * (tl + 64 * 9) + 2 <= SIG_LEN);
    if (inb) {
        #pragma unroll
        for (int m = 0; m < 10; m++)
            xs[m] = *(const float2*)(x + st0 + 2 * (tl + 64 * m));
    } else {
        #pragma unroll
        for (int m = 0; m < 10; m++) {
            int i0 = st0 + 2 * (tl + 64 * m);
            xs[m].x = (i0     >= 0 && i0     < SIG_LEN) ? x[i0]     : 0.0f;
            xs[m].y = (i0 + 1 >= 0 && i0 + 1 < SIG_LEN) ? x[i0 + 1] : 0.0f;
        }
    }
    #pragma unroll
    for (int m = 0; m < 8; m++) {
        float2 w = TAB.win[tl + 64 * m];
        v[m].re = vmul(pk(xs[m].x, xs[m + 2].x), pk(w.x, w.x));
        v[m].im = vmul(pk(xs[m].y, xs[m + 2].y), pk(w.y, w.y));
    }

    // ---- stage 1: fft8 + twiddle powers of tw512[tl] (interleaved: only w1..w4 live) ----
    fft8p(v);
    {
        float2 w1s = TAB.tw512[tl];
        cp w1 = { pk(w1s.x, w1s.x), pk(w1s.y, w1s.y) };
        v[1] = cpmul(v[1], w1);
        cp w2 = cpmul(w1, w1);
        v[2] = cpmul(v[2], w2);
        cp w3 = cpmul(w2, w1);
        v[3] = cpmul(v[3], w3);
        cp w4 = cpmul(w2, w2);
        v[4] = cpmul(v[4], w4);
        v[5] = cpmul(v[5], cpmul(w4, w1));
        v[6] = cpmul(v[6], cpmul(w3, w3));
        v[7] = cpmul(v[7], cpmul(w4, w3));
    }
    ulonglong2* bufA = sA[pr];
    #pragma unroll
    for (int j = 0; j < 8; j++)
        bufA[j * 64 + (((hi ^ j) & 7) << 3) + lo] = make_ulonglong2(v[j].re, v[j].im);
    __syncthreads();

    // ---- stage 2 (read all -> sync -> overwrite same buffer) ----
    #pragma unroll
    for (int m = 0; m < 8; m++) {
        ulonglong2 e = bufA[hi * 64 + (((m ^ hi) & 7) << 3) + lo];
        v[m].re = e.x; v[m].im = e.y;
    }
    fft8p(v);
    #pragma unroll
    for (int j2 = 1; j2 < 8; j2++) {
        float2 wd = TAB.tw64[j2 * 8 + lo];
        cp w = { pk(wd.x, wd.x), pk(wd.y, wd.y) };
        v[j2] = cpmul(v[j2], w);
    }
    __syncthreads();
    #pragma unroll
    for (int j2 = 0; j2 < 8; j2++)
        bufA[j2 * 64 + hi * 8 + (lo ^ j2)] = make_ulonglong2(v[j2].re, v[j2].im);
    __syncthreads();

    // ---- stage 3 ----
    #pragma unroll
    for (int n0 = 0; n0 < 8; n0++) {
        ulonglong2 e = bufA[lo * 64 + hi * 8 + (n0 ^ lo)];
        v[n0].re = e.x; v[n0].im = e.y;
    }
    fft8p(v);
    __syncthreads();
    #pragma unroll
    for (int j3 = 0; j3 < 8; j3++) {
        int k = hi + 8 * lo + 64 * j3;
        bufA[k ^ lo] = make_ulonglong2(v[j3].re, v[j3].im);   // addrR(k)=k^((k>>3)&7)
    }
    __syncthreads();

    // ---- conjugate-pair untangle (packed) + (-1)^k shift + mag/phase ----
    float* om0 = out + (size_t)f0 * HALF;
    float* op0 = out + (size_t)N_ROWS * HALF + (size_t)f0 * HALF;
    float* om1 = om0 + HALF;
    float* op1 = op0 + HALF;
    const bool w0 = (f0 < N_FRAMES);
    const bool w1 = (f1 < N_FRAMES);
    const u64 Hd = pk(0.5f, 0.5f);

    const float sg = (tl & 1) ? -1.0f : 1.0f;
    const float ng = -sg;
    #pragma unroll
    for (int q = 0; q < 4; q++) {
        int k  = tl + 64 * q;                  // 0..255
        int ka = k & 511, kb = (512 - k) & 511;
        ulonglong2 ek = bufA[ka ^ ((ka >> 3) & 7)];
        ulonglong2 em = bufA[kb ^ ((kb >> 3) & 7)];
        cp zk = { ek.x, ek.y }, zm = { em.x, em.y };
        u64 Ar = vmul(vadd(zk.re, zm.re), Hd);
        u64 Ai = vmul(vsub(zk.im, zm.im), Hd);
        u64 Br = vmul(vsub(zk.re, zm.re), Hd);
        u64 Bi = vmul(vadd(zk.im, zm.im), Hd);
        float2 wd = TAB.tw1024[k];
        u64 wc = pk(wd.x, wd.x), ws = pk(wd.y, wd.y);
        u64 wbr = vsub(vmul(wc, Br), vmul(ws, Bi));
        u64 wbi = vfma(wc, Bi, vmul(ws, Br));
        u64 Xkr = vadd(Ar, wbi), Xki = vsub(Ai, wbr);
        u64 Xmr = vsub(Ar, wbi), nXmi = vadd(Ai, wbr);   // Xmi = -nXmi (sign folded below)
        u64 Mk = vfma(Xki, Xki, vmul(Xkr, Xkr));
        u64 Mm = vfma(nXmi, nXmi, vmul(Xmr, Xmr));
        float mk0, mk1, mm0, mm1, kr0, kr1, ki0, ki1, mr0, mr1, ni0, ni1;
        upk(mk0, mk1, Mk); upk(mm0, mm1, Mm);
        upk(kr0, kr1, Xkr); upk(ki0, ki1, Xki);
        upk(mr0, mr1, Xmr); upk(ni0, ni1, nXmi);
        int m = 512 - k;
        if (w0) {
            float rk = fsqrt_fast(mk0), rm = fsqrt_fast(mm0);
            float tk, tm;
            fatan2_half2(sg * ki0, sg * kr0, rk, ng * ni0, sg * mr0, rm, tk, tm);
            om0[k] = rk; op0[k] = tk;
            om0[m] = rm; op0[m] = tm;
        }
        if (w1) {
            float rk = fsqrt_fast(mk1), rm = fsqrt_fast(mm1);
            float tk, tm;
            fatan2_half2(sg * ki1, sg * kr1, rk, ng * ni1, sg * mr1, rm, tk, tm);
            om1[k] = rk; op1[k] = tk;
            om1[m] = rm; op1[m] = tm;
        }
    }
    if (tl == 0) {                      // center bin k=256: X = conj(Z256), even parity
        ulonglong2 e = bufA[256];       // 256 ^ ((256>>3)&7) == 256
        float zr0, zr1, zi0, zi1;
        upk(zr0, zr1, e.x); upk(zi0, zi1, e.y);
        if (w0) {
            float r = fsqrt_fast(zr0 * zr0 + zi0 * zi0);
            om0[256] = r; op0[256] = fatan2_half(-zi0, zr0, r);
        }
        if (w1) {
            float r = fsqrt_fast(zr1 * zr1 + zi1 * zi1);
            om1[256] = r; op1[256] = fatan2_half(-zi1, zr1, r);
        }
    }

    // ---- zero-fill rows in [N_FRAMES, N_ROWS) ----
    #pragma unroll
    for (int h = 0; h < 2; h++) {
        int f = f0 + h;
        if (f >= N_FRAMES && f < N_ROWS) {
            float* zm = out + (size_t)f * HALF;
            float* zp = out + (size_t)N_ROWS * HALF + (size_t)f * HALF;
            for (int k = tl; k < HALF; k += 64) { zm[k] = 0.0f; zp[k] = 0.0f; }
        }
    }
}

extern "C" void kernel_launch(void* const* d_in, const int* in_sizes, int n_in,
                              void* d_out, int out_size) {
    const float* x = (const float*)d_in[0];
    float* out = (float*)d_out;
    stft_kernel<<<(N_ROWS + 3) / 4, 128>>>(x, out);
}

// round 12
// speedup vs baseline: 1.5768x; 1.5768x over previous
#include <cuda_runtime.h>

#define SIG_LEN  16777216
#define HOP      256
#define PAD      768
#define N_FRAMES 65539
#define N_ROWS   65542
#define HALF     513

// ---------------- compile-time tables (correctly-rounded, double precision) ----------------
constexpr double PI_D = 3.141592653589793238462643383279502884;

constexpr double tcos(double x) {
    double x2 = x * x, term = 1.0, s = 1.0;
    for (int i = 1; i <= 10; i++) { term *= -x2 / ((2.0 * i - 1.0) * (2.0 * i)); s += term; }
    return s;
}
constexpr double tsin(double x) {
    double x2 = x * x, term = x, s = x;
    for (int i = 1; i <= 10; i++) { term *= -x2 / ((2.0 * i) * (2.0 * i + 1.0)); s += term; }
    return s;
}
constexpr double cpi(double t) {
    while (t >= 2.0) t -= 2.0;
    while (t < 0.0) t += 2.0;
    if (t > 1.0) t = 2.0 - t;
    double sg = 1.0;
    if (t > 0.5) { t = 1.0 - t; sg = -1.0; }
    return sg * (t <= 0.25 ? tcos(PI_D * t) : tsin(PI_D * (0.5 - t)));
}
constexpr double spi(double t) {
    while (t >= 2.0) t -= 2.0;
    while (t < 0.0) t += 2.0;
    double sg = 1.0;
    if (t > 1.0) { t -= 1.0; sg = -1.0; }
    if (t > 0.5) t = 1.0 - t;
    return sg * (t <= 0.25 ? tsin(PI_D * t) : tcos(PI_D * (0.5 - t)));
}

struct Tables {
    float2 tw512[512];    // e^{-2pi i k/512}
    float2 tw64[64];      // {c,s} e^{-2pi i n0 j2/64}
    float2 tw1024[513];   // {c,s} e^{-i pi k/512}
    float2 win[512];      // (w[2n], w[2n+1]) / 32
};
constexpr Tables mk_tables() {
    Tables T{};
    for (int k = 0; k < 512; k++)
        T.tw512[k] = float2{ (float)cpi(k / 256.0), (float)(-spi(k / 256.0)) };
    for (int j2 = 0; j2 < 8; j2++)
        for (int n0 = 0; n0 < 8; n0++)
            T.tw64[j2 * 8 + n0] = float2{ (float)cpi(n0 * j2 / 32.0),
                                          (float)(-spi(n0 * j2 / 32.0)) };
    for (int k = 0; k <= 512; k++)
        T.tw1024[k] = float2{ (float)cpi(k / 512.0), (float)(-spi(k / 512.0)) };
    for (int n = 0; n < 512; n++)
        T.win[n] = float2{ (float)((0.54 - 0.46 * cpi(2.0 * (2 * n) / 1023.0)) / 32.0),
                           (float)((0.54 - 0.46 * cpi(2.0 * (2 * n + 1) / 1023.0)) / 32.0) };
    return T;
}
__device__ constexpr Tables TAB = mk_tables();

// ---------------- f32x2 packed primitives (2 frames in the 2 lanes) ----------------
typedef unsigned long long u64;

__device__ __forceinline__ u64 pk(float lo, float hi) {
    u64 r; asm("mov.b64 %0, {%1, %2};" : "=l"(r) : "f"(lo), "f"(hi)); return r;
}
__device__ __forceinline__ void upk(float& lo, float& hi, u64 v) {
    asm("mov.b64 {%0, %1}, %2;" : "=f"(lo), "=f"(hi) : "l"(v));
}
__device__ __forceinline__ u64 vadd(u64 a, u64 b) {
    u64 r; asm("add.rn.f32x2 %0, %1, %2;" : "=l"(r) : "l"(a), "l"(b)); return r;
}
__device__ __forceinline__ u64 vmul(u64 a, u64 b) {
    u64 r; asm("mul.rn.f32x2 %0, %1, %2;" : "=l"(r) : "l"(a), "l"(b)); return r;
}
__device__ __forceinline__ u64 vfma(u64 a, u64 b, u64 c) {
    u64 r; asm("fma.rn.f32x2 %0, %1, %2, %3;" : "=l"(r) : "l"(a), "l"(b), "l"(c)); return r;
}
__device__ __forceinline__ u64 vneg1() { return pk(-1.0f, -1.0f); }
__device__ __forceinline__ u64 vsub(u64 a, u64 b) { return vfma(b, vneg1(), a); }  // exact a-b

struct cp { u64 re, im; };
__device__ __forceinline__ cp cadd(cp a, cp b)   { return { vadd(a.re, b.re), vadd(a.im, b.im) }; }
__device__ __forceinline__ cp csub(cp a, cp b)   { return { vsub(a.re, b.re), vsub(a.im, b.im) }; }
// a + (-i)b = (are+bim, aim-bre);  a - (-i)b = (are-bim, aim+bre)
__device__ __forceinline__ cp caddmi(cp a, cp b) { return { vadd(a.re, b.im), vsub(a.im, b.re) }; }
__device__ __forceinline__ cp csubmi(cp a, cp b) { return { vsub(a.re, b.im), vadd(a.im, b.re) }; }
__device__ __forceinline__ cp cpmul(cp a, cp b) {
    cp r;
    r.re = vsub(vmul(a.re, b.re), vmul(a.im, b.im));
    r.im = vfma(a.re, b.im, vmul(a.im, b.re));
    return r;
}

__device__ __forceinline__ float fsqrt_fast(float x) {
    float r; asm("sqrt.approx.f32 %0, %1;" : "=f"(r) : "f"(x)); return r;
}

// Half-angle atan2 (scalar) reusing r = |X| (already computed for magnitude).
//   x >= 0: theta = 2*atan(y/(r+|x|));  x < 0: theta = sign(y)*pi - 2*atan(y/(r+|x|))
// 6-coeff odd minimax for atan on [-1,1] (abs err ~1e-5 rad). Sign via (y<0)
// comparison: y==-0.0 & x<0 -> +pi, matching the reference at the Nyquist bin
// (our pair formula makes Im = -0.0 there; rfft reference has +0).
__device__ __forceinline__ float fatan2_half(float y, float x, float r) {
    const float PI = 3.14159265358979323f;
    float den = r + fabsf(x);
    float t = __fdividef(y, den);
    t = (den == 0.0f) ? 0.0f : t;          // atan2(0,0) = 0
    float s = t * t;
    float p = fmaf(fmaf(fmaf(fmaf(fmaf(-0.02344240f, s, 0.10530664f), s,
                 -0.23286574f), s, 0.38708692f), s, -0.66524694f), s, 1.99995452f);
    float th = t * p;                       // 2*atan(t)
    if (x < 0.0f) th = ((y < 0.0f) ? -PI : PI) - th;
    return th;
}

// packed 8-point DFT (both frames simultaneously)
__device__ __forceinline__ void fft8p(cp* a) {
    const float Cf = 0.70710678118654752440f;
    u64 Cd = pk(Cf, Cf), nCd = pk(-Cf, -Cf);
    cp s0 = cadd(a[0], a[4]), s1 = csub(a[0], a[4]);
    cp s2 = cadd(a[2], a[6]), s3 = csub(a[2], a[6]);
    cp t0 = cadd(a[1], a[5]), t1 = csub(a[1], a[5]);
    cp t2 = cadd(a[3], a[7]), t3 = csub(a[3], a[7]);
    cp E0 = cadd(s0, s2), E2 = csub(s0, s2);
    cp E1 = caddmi(s1, s3), E3 = csubmi(s1, s3);
    cp O0 = cadd(t0, t2), O2 = csub(t0, t2);
    cp O1 = caddmi(t1, t3), O3 = csubmi(t1, t3);
    cp W1 = { vmul(vadd(O1.re, O1.im), Cd), vmul(vsub(O1.im, O1.re), Cd) };
    cp W3 = { vmul(vsub(O3.im, O3.re), Cd), vmul(vadd(O3.re, O3.im), nCd) };
    a[0] = cadd(E0, O0);   a[4] = csub(E0, O0);
    a[1] = cadd(E1, W1);   a[5] = csub(E1, W1);
    a[2] = caddmi(E2, O2); a[6] = csubmi(E2, O2);   // W2 = -i*O2 folded
    a[3] = cadd(E3, W3);   a[7] = csub(E3, W3);
}

// ---------------- fused STFT kernel: 128 threads, 2 frame-pairs (4 frames)/block ----------
// R9 structure: batched xs[10] input loads (MLP~10), scalar half-angle atan2,
// launch_bounds(128,8); only change vs R9: de-duplicated float2 twiddle tables.
__global__ __launch_bounds__(128, 8) void stft_kernel(const float* __restrict__ x,
                                                      float* __restrict__ out) {
    __shared__ ulonglong2 sA[2][512];

    const int t  = threadIdx.x;
    const int pr = t >> 6;            // frame-pair slot (0-1)
    const int tl = t & 63;
    const int f0 = blockIdx.x * 4 + pr * 2;   // lane .x frame
    const int f1 = f0 + 1;                    // lane .y frame
    const int st0 = f0 * HOP - PAD;
    const int hi = tl >> 3, lo = tl & 7;

    cp v[8];

    // ---- load (batched; frame1 sample n == frame0 sample n+128, index m+2) + window ----
    float2 xs[10];
    const bool inb = (st0 >= 0) && (st0 + 2 * (tl + 64 * 9) + 2 <= SIG_LEN);
    if (inb) {
        #pragma unroll
        for (int m = 0; m < 10; m++)
            xs[m] = *(const float2*)(x + st0 + 2 * (tl + 64 * m));
    } else {
        #pragma unroll
        for (int m = 0; m < 10; m++) {
            int i0 = st0 + 2 * (tl + 64 * m);
            xs[m].x = (i0     >= 0 && i0     < SIG_LEN) ? x[i0]     : 0.0f;
            xs[m].y = (i0 + 1 >= 0 && i0 + 1 < SIG_LEN) ? x[i0 + 1] : 0.0f;
        }
    }
    #pragma unroll
    for (int m = 0; m < 8; m++) {
        float2 w = TAB.win[tl + 64 * m];
        v[m].re = vmul(pk(xs[m].x, xs[m + 2].x), pk(w.x, w.x));
        v[m].im = vmul(pk(xs[m].y, xs[m + 2].y), pk(w.y, w.y));
    }

    // ---- stage 1: fft8 + twiddle powers of tw512[tl] (interleaved: only w1..w4 live) ----
    fft8p(v);
    {
        float2 w1s = TAB.tw512[tl];
        cp w1 = { pk(w1s.x, w1s.x), pk(w1s.y, w1s.y) };
        v[1] = cpmul(v[1], w1);
        cp w2 = cpmul(w1, w1);
        v[2] = cpmul(v[2], w2);
        cp w3 = cpmul(w2, w1);
        v[3] = cpmul(v[3], w3);
        cp w4 = cpmul(w2, w2);
        v[4] = cpmul(v[4], w4);
        v[5] = cpmul(v[5], cpmul(w4, w1));
        v[6] = cpmul(v[6], cpmul(w3, w3));
        v[7] = cpmul(v[7], cpmul(w4, w3));
    }
    ulonglong2* bufA = sA[pr];
    #pragma unroll
    for (int j = 0; j < 8; j++)
        bufA[j * 64 + (((hi ^ j) & 7) << 3) + lo] = make_ulonglong2(v[j].re, v[j].im);
    __syncthreads();

    // ---- stage 2 (read all -> sync -> overwrite same buffer) ----
    #pragma unroll
    for (int m = 0; m < 8; m++) {
        ulonglong2 e = bufA[hi * 64 + (((m ^ hi) & 7) << 3) + lo];
        v[m].re = e.x; v[m].im = e.y;
    }
    fft8p(v);
    #pragma unroll
    for (int j2 = 1; j2 < 8; j2++) {
        float2 wd = TAB.tw64[j2 * 8 + lo];
        cp w = { pk(wd.x, wd.x), pk(wd.y, wd.y) };
        v[j2] = cpmul(v[j2], w);
    }
    __syncthreads();
    #pragma unroll
    for (int j2 = 0; j2 < 8; j2++)
        bufA[j2 * 64 + hi * 8 + (lo ^ j2)] = make_ulonglong2(v[j2].re, v[j2].im);
    __syncthreads();

    // ---- stage 3 ----
    #pragma unroll
    for (int n0 = 0; n0 < 8; n0++) {
        ulonglong2 e = bufA[lo * 64 + hi * 8 + (n0 ^ lo)];
        v[n0].re = e.x; v[n0].im = e.y;
    }
    fft8p(v);
    __syncthreads();
    #pragma unroll
    for (int j3 = 0; j3 < 8; j3++) {
        int k = hi + 8 * lo + 64 * j3;
        bufA[k ^ lo] = make_ulonglong2(v[j3].re, v[j3].im);   // addrR(k)=k^((k>>3)&7)
    }
    __syncthreads();

    // ---- conjugate-pair untangle (packed) + (-1)^k shift + mag/phase (scalar/frame) ----
    float* om0 = out + (size_t)f0 * HALF;
    float* op0 = out + (size_t)N_ROWS * HALF + (size_t)f0 * HALF;
    float* om1 = om0 + HALF;
    float* op1 = op0 + HALF;
    const bool w0 = (f0 < N_FRAMES);
    const bool w1 = (f1 < N_FRAMES);
    const u64 Hd = pk(0.5f, 0.5f);

    const float sg = (tl & 1) ? -1.0f : 1.0f;
    const float ng = -sg;
    #pragma unroll
    for (int q = 0; q < 4; q++) {
        int k  = tl + 64 * q;                  // 0..255
        int ka = k & 511, kb = (512 - k) & 511;
        ulonglong2 ek = bufA[ka ^ ((ka >> 3) & 7)];
        ulonglong2 em = bufA[kb ^ ((kb >> 3) & 7)];
        cp zk = { ek.x, ek.y }, zm = { em.x, em.y };
        u64 Ar = vmul(vadd(zk.re, zm.re), Hd);
        u64 Ai = vmul(vsub(zk.im, zm.im), Hd);
        u64 Br = vmul(vsub(zk.re, zm.re), Hd);
        u64 Bi = vmul(vadd(zk.im, zm.im), Hd);
        float2 wd = TAB.tw1024[k];
        u64 wc = pk(wd.x, wd.x), ws = pk(wd.y, wd.y);
        u64 wbr = vsub(vmul(wc, Br), vmul(ws, Bi));
        u64 wbi = vfma(wc, Bi, vmul(ws, Br));
        u64 Xkr = vadd(Ar, wbi), Xki = vsub(Ai, wbr);
        u64 Xmr = vsub(Ar, wbi), nXmi = vadd(Ai, wbr);   // Xmi = -nXmi (sign folded below)
        u64 Mk = vfma(Xki, Xki, vmul(Xkr, Xkr));
        u64 Mm = vfma(nXmi, nXmi, vmul(Xmr, Xmr));
        float mk0, mk1, mm0, mm1, kr0, kr1, ki0, ki1, mr0, mr1, ni0, ni1;
        upk(mk0, mk1, Mk); upk(mm0, mm1, Mm);
        upk(kr0, kr1, Xkr); upk(ki0, ki1, Xki);
        upk(mr0, mr1, Xmr); upk(ni0, ni1, nXmi);
        int m = 512 - k;
        if (w0) {
            float rk = fsqrt_fast(mk0), rm = fsqrt_fast(mm0);
            om0[k] = rk; op0[k] = fatan2_half(sg * ki0, sg * kr0, rk);
            om0[m] = rm; op0[m] = fatan2_half(ng * ni0, sg * mr0, rm);
        }
        if (w1) {
            float rk = fsqrt_fast(mk1), rm = fsqrt_fast(mm1);
            om1[k] = rk; op1[k] = fatan2_half(sg * ki1, sg * kr1, rk);
            om1[m] = rm; op1[m] = fatan2_half(ng * ni1, sg * mr1, rm);
        }
    }
    if (tl == 0) {                      // center bin k=256: X = conj(Z256), even parity
        ulonglong2 e = bufA[256];       // 256 ^ ((256>>3)&7) == 256
        float zr0, zr1, zi0, zi1;
        upk(zr0, zr1, e.x); upk(zi0, zi1, e.y);
        if (w0) {
            float r = fsqrt_fast(zr0 * zr0 + zi0 * zi0);
            om0[256] = r; op0[256] = fatan2_half(-zi0, zr0, r);
        }
        if (w1) {
            float r = fsqrt_fast(zr1 * zr1 + zi1 * zi1);
            om1[256] = r; op1[256] = fatan2_half(-zi1, zr1, r);
        }
    }

    // ---- zero-fill rows in [N_FRAMES, N_ROWS) ----
    #pragma unroll
    for (int h = 0; h < 2; h++) {
        int f = f0 + h;
        if (f >= N_FRAMES && f < N_ROWS) {
            float* zm = out + (size_t)f * HALF;
            float* zp = out + (size_t)N_ROWS * HALF + (size_t)f * HALF;
            for (int k = tl; k < HALF; k += 64) { zm[k] = 0.0f; zp[k] = 0.0f; }
        }
    }
}

extern "C" void kernel_launch(void* const* d_in, const int* in_sizes, int n_in,
                              void* d_out, int out_size) {
    const float* x = (const float*)d_in[0];
    float* out = (float*)d_out;
    stft_kernel<<<(N_ROWS + 3) / 4, 128>>>(x, out);
}

// round 14
// speedup vs baseline: 1.6252x; 1.0307x over previous
#include <cuda_runtime.h>

#define SIG_LEN  16777216
#define HOP      256
#define PAD      768
#define N_FRAMES 65539
#define N_ROWS   65542
#define HALF     513

// ---------------- compile-time tables (correctly-rounded, double precision) ----------------
constexpr double PI_D = 3.141592653589793238462643383279502884;

constexpr double tcos(double x) {
    double x2 = x * x, term = 1.0, s = 1.0;
    for (int i = 1; i <= 10; i++) { term *= -x2 / ((2.0 * i - 1.0) * (2.0 * i)); s += term; }
    return s;
}
constexpr double tsin(double x) {
    double x2 = x * x, term = x, s = x;
    for (int i = 1; i <= 10; i++) { term *= -x2 / ((2.0 * i) * (2.0 * i + 1.0)); s += term; }
    return s;
}
constexpr double cpi(double t) {
    while (t >= 2.0) t -= 2.0;
    while (t < 0.0) t += 2.0;
    if (t > 1.0) t = 2.0 - t;
    double sg = 1.0;
    if (t > 0.5) { t = 1.0 - t; sg = -1.0; }
    return sg * (t <= 0.25 ? tcos(PI_D * t) : tsin(PI_D * (0.5 - t)));
}
constexpr double spi(double t) {
    while (t >= 2.0) t -= 2.0;
    while (t < 0.0) t += 2.0;
    double sg = 1.0;
    if (t > 1.0) { t -= 1.0; sg = -1.0; }
    if (t > 0.5) t = 1.0 - t;
    return sg * (t <= 0.25 ? tsin(PI_D * t) : tcos(PI_D * (0.5 - t)));
}

struct Tables {
    float2 tw512[512];    // e^{-2pi i k/512}
    float2 tw64[64];      // {c,s} e^{-2pi i n0 j2/64}
    float2 tw1024[513];   // {c,s} e^{-i pi k/512}
    float2 win[512];      // (w[2n], w[2n+1]) / 32
};
constexpr Tables mk_tables() {
    Tables T{};
    for (int k = 0; k < 512; k++)
        T.tw512[k] = float2{ (float)cpi(k / 256.0), (float)(-spi(k / 256.0)) };
    for (int j2 = 0; j2 < 8; j2++)
        for (int n0 = 0; n0 < 8; n0++)
            T.tw64[j2 * 8 + n0] = float2{ (float)cpi(n0 * j2 / 32.0),
                                          (float)(-spi(n0 * j2 / 32.0)) };
    for (int k = 0; k <= 512; k++)
        T.tw1024[k] = float2{ (float)cpi(k / 512.0), (float)(-spi(k / 512.0)) };
    for (int n = 0; n < 512; n++)
        T.win[n] = float2{ (float)((0.54 - 0.46 * cpi(2.0 * (2 * n) / 1023.0)) / 32.0),
                           (float)((0.54 - 0.46 * cpi(2.0 * (2 * n + 1) / 1023.0)) / 32.0) };
    return T;
}
__device__ constexpr Tables TAB = mk_tables();

// ---------------- f32x2 packed primitives (2 frames in the 2 lanes) ----------------
typedef unsigned long long u64;

__device__ __forceinline__ u64 pk(float lo, float hi) {
    u64 r; asm("mov.b64 %0, {%1, %2};" : "=l"(r) : "f"(lo), "f"(hi)); return r;
}
__device__ __forceinline__ void upk(float& lo, float& hi, u64 v) {
    asm("mov.b64 {%0, %1}, %2;" : "=f"(lo), "=f"(hi) : "l"(v));
}
__device__ __forceinline__ u64 vadd(u64 a, u64 b) {
    u64 r; asm("add.rn.f32x2 %0, %1, %2;" : "=l"(r) : "l"(a), "l"(b)); return r;
}
__device__ __forceinline__ u64 vmul(u64 a, u64 b) {
    u64 r; asm("mul.rn.f32x2 %0, %1, %2;" : "=l"(r) : "l"(a), "l"(b)); return r;
}
__device__ __forceinline__ u64 vfma(u64 a, u64 b, u64 c) {
    u64 r; asm("fma.rn.f32x2 %0, %1, %2, %3;" : "=l"(r) : "l"(a), "l"(b), "l"(c)); return r;
}
__device__ __forceinline__ u64 vneg1() { return pk(-1.0f, -1.0f); }
__device__ __forceinline__ u64 vsub(u64 a, u64 b) { return vfma(b, vneg1(), a); }  // exact a-b

struct cp { u64 re, im; };
__device__ __forceinline__ cp cadd(cp a, cp b)   { return { vadd(a.re, b.re), vadd(a.im, b.im) }; }
__device__ __forceinline__ cp csub(cp a, cp b)   { return { vsub(a.re, b.re), vsub(a.im, b.im) }; }
// a + (-i)b = (are+bim, aim-bre);  a - (-i)b = (are-bim, aim+bre)
__device__ __forceinline__ cp caddmi(cp a, cp b) { return { vadd(a.re, b.im), vsub(a.im, b.re) }; }
__device__ __forceinline__ cp csubmi(cp a, cp b) { return { vsub(a.re, b.im), vadd(a.im, b.re) }; }
__device__ __forceinline__ cp cpmul(cp a, cp b) {
    cp r;
    r.re = vsub(vmul(a.re, b.re), vmul(a.im, b.im));
    r.im = vfma(a.re, b.im, vmul(a.im, b.re));
    return r;
}

__device__ __forceinline__ float fsqrt_fast(float x) {
    float r; asm("sqrt.approx.f32 %0, %1;" : "=f"(r) : "f"(x)); return r;
}

// Half-angle atan2 (scalar) reusing r = |X| (already computed for magnitude).
//   x >= 0: theta = 2*atan(y/(r+|x|));  x < 0: theta = sign(y)*pi - 2*atan(y/(r+|x|))
// 5-coeff odd minimax for atan on [-1,1] (abs err ~1e-5, x2 for half-angle -> ~2e-5 rad;
// budget ~1.45e-3 rad rms). Sign via (y<0) comparison: y==-0.0 & x<0 -> +pi, matching
// the reference at the Nyquist bin (our pair formula makes Im = -0.0 there; rfft has +0).
__device__ __forceinline__ float fatan2_half(float y, float x, float r) {
    const float PI = 3.14159265358979323f;
    float den = r + fabsf(x);
    float t = __fdividef(y, den);
    t = (den == 0.0f) ? 0.0f : t;          // atan2(0,0) = 0
    float s = t * t;
    float p = fmaf(fmaf(fmaf(fmaf(0.0416702f, s, -0.1702660f), s,
                 0.3602820f), s, -0.6605990f), s, 1.9997320f);
    float th = t * p;                       // 2*atan(t)
    if (x < 0.0f) th = ((y < 0.0f) ? -PI : PI) - th;
    return th;
}

// packed 8-point DFT (both frames simultaneously)
__device__ __forceinline__ void fft8p(cp* a) {
    const float Cf = 0.70710678118654752440f;
    u64 Cd = pk(Cf, Cf), nCd = pk(-Cf, -Cf);
    cp s0 = cadd(a[0], a[4]), s1 = csub(a[0], a[4]);
    cp s2 = cadd(a[2], a[6]), s3 = csub(a[2], a[6]);
    cp t0 = cadd(a[1], a[5]), t1 = csub(a[1], a[5]);
    cp t2 = cadd(a[3], a[7]), t3 = csub(a[3], a[7]);
    cp E0 = cadd(s0, s2), E2 = csub(s0, s2);
    cp E1 = caddmi(s1, s3), E3 = csubmi(s1, s3);
    cp O0 = cadd(t0, t2), O2 = csub(t0, t2);
    cp O1 = caddmi(t1, t3), O3 = csubmi(t1, t3);
    cp W1 = { vmul(vadd(O1.re, O1.im), Cd), vmul(vsub(O1.im, O1.re), Cd) };
    cp W3 = { vmul(vsub(O3.im, O3.re), Cd), vmul(vadd(O3.re, O3.im), nCd) };
    a[0] = cadd(E0, O0);   a[4] = csub(E0, O0);
    a[1] = cadd(E1, W1);   a[5] = csub(E1, W1);
    a[2] = caddmi(E2, O2); a[6] = csubmi(E2, O2);   // W2 = -i*O2 folded
    a[3] = cadd(E3, W3);   a[7] = csub(E3, W3);
}

// ---------------- fused STFT kernel: 128 threads, 2 frame-pairs (4 frames)/block ----------
__global__ __launch_bounds__(128, 8) void stft_kernel(const float* __restrict__ x,
                                                      float* __restrict__ out) {
    __shared__ ulonglong2 sA[2][512];

    const int t  = threadIdx.x;
    const int pr = t >> 6;            // frame-pair slot (0-1)
    const int tl = t & 63;
    const int f0 = blockIdx.x * 4 + pr * 2;   // lane .x frame
    const int f1 = f0 + 1;                    // lane .y frame
    const int st0 = f0 * HOP - PAD;
    const int hi = tl >> 3, lo = tl & 7;

    cp v[8];

    // ---- load (batched; frame1 sample n == frame0 sample n+128, index m+2) + window ----
    float2 xs[10];
    const bool inb = (st0 >= 0) && (st0 + 2 * (tl + 64 * 9) + 2 <= SIG_LEN);
    if (inb) {
        #pragma unroll
        for (int m = 0; m < 10; m++)
            xs[m] = *(const float2*)(x + st0 + 2 * (tl + 64 * m));
    } else {
        #pragma unroll
        for (int m = 0; m < 10; m++) {
            int i0 = st0 + 2 * (tl + 64 * m);
            xs[m].x = (i0     >= 0 && i0     < SIG_LEN) ? x[i0]     : 0.0f;
            xs[m].y = (i0 + 1 >= 0 && i0 + 1 < SIG_LEN) ? x[i0 + 1] : 0.0f;
        }
    }
    #pragma unroll
    for (int m = 0; m < 8; m++) {
        float2 w = TAB.win[tl + 64 * m];
        v[m].re = vmul(pk(xs[m].x, xs[m + 2].x), pk(w.x, w.x));
        v[m].im = vmul(pk(xs[m].y, xs[m + 2].y), pk(w.y, w.y));
    }

    // ---- stage 1: fft8 + twiddle powers of tw512[tl] (interleaved: only w1..w4 live) ----
    fft8p(v);
    {
        float2 w1s = TAB.tw512[tl];
        cp w1 = { pk(w1s.x, w1s.x), pk(w1s.y, w1s.y) };
        v[1] = cpmul(v[1], w1);
        cp w2 = cpmul(w1, w1);
        v[2] = cpmul(v[2], w2);
        cp w3 = cpmul(w2, w1);
        v[3] = cpmul(v[3], w3);
        cp w4 = cpmul(w2, w2);
        v[4] = cpmul(v[4], w4);
        v[5] = cpmul(v[5], cpmul(w4, w1));
        v[6] = cpmul(v[6], cpmul(w3, w3));
        v[7] = cpmul(v[7], cpmul(w4, w3));
    }
    ulonglong2* bufA = sA[pr];
    #pragma unroll
    for (int j = 0; j < 8; j++)
        bufA[j * 64 + (((hi ^ j) & 7) << 3) + lo] = make_ulonglong2(v[j].re, v[j].im);
    __syncthreads();

    // ---- stage 2 (read all -> sync -> overwrite same buffer) ----
    #pragma unroll
    for (int m = 0; m < 8; m++) {
        ulonglong2 e = bufA[hi * 64 + (((m ^ hi) & 7) << 3) + lo];
        v[m].re = e.x; v[m].im = e.y;
    }
    fft8p(v);
    #pragma unroll
    for (int j2 = 1; j2 < 8; j2++) {
        float2 wd = TAB.tw64[j2 * 8 + lo];
        cp w = { pk(wd.x, wd.x), pk(wd.y, wd.y) };
        v[j2] = cpmul(v[j2], w);
    }
    __syncthreads();
    #pragma unroll
    for (int j2 = 0; j2 < 8; j2++)
        bufA[j2 * 64 + hi * 8 + (lo ^ j2)] = make_ulonglong2(v[j2].re, v[j2].im);
    __syncthreads();

    // ---- stage 3 ----
    #pragma unroll
    for (int n0 = 0; n0 < 8; n0++) {
        ulonglong2 e = bufA[lo * 64 + hi * 8 + (n0 ^ lo)];
        v[n0].re = e.x; v[n0].im = e.y;
    }
    fft8p(v);
    __syncthreads();
    #pragma unroll
    for (int j3 = 0; j3 < 8; j3++) {
        int k = hi + 8 * lo + 64 * j3;
        bufA[k ^ lo] = make_ulonglong2(v[j3].re, v[j3].im);   // addrR(k)=k^((k>>3)&7)
    }
    __syncthreads();

    // ---- conjugate-pair untangle (packed) + (-1)^k shift (packed) + mag/phase ----
    float* om0 = out + (size_t)f0 * HALF;
    float* op0 = out + (size_t)N_ROWS * HALF + (size_t)f0 * HALF;
    float* om1 = om0 + HALF;
    float* op1 = op0 + HALF;
    const bool w0 = (f0 < N_FRAMES);
    const bool w1 = (f1 < N_FRAMES);
    const u64 Hd = pk(0.5f, 0.5f);

    const float sg = (tl & 1) ? -1.0f : 1.0f;   // (-1)^k for k = tl+64q (and 512-k)
    const u64 sgv = pk(sg, sg);
    const u64 ngv = pk(-sg, -sg);
    #pragma unroll
    for (int q = 0; q < 4; q++) {
        int k  = tl + 64 * q;                  // 0..255
        int ka = k & 511, kb = (512 - k) & 511;
        ulonglong2 ek = bufA[ka ^ ((ka >> 3) & 7)];
        ulonglong2 em = bufA[kb ^ ((kb >> 3) & 7)];
        cp zk = { ek.x, ek.y }, zm = { em.x, em.y };
        u64 Ar = vmul(vadd(zk.re, zm.re), Hd);
        u64 Ai = vmul(vsub(zk.im, zm.im), Hd);
        u64 Br = vmul(vsub(zk.re, zm.re), Hd);
        u64 Bi = vmul(vadd(zk.im, zm.im), Hd);
        float2 wd = TAB.tw1024[k];
        u64 wc = pk(wd.x, wd.x), ws = pk(wd.y, wd.y);
        u64 wbr = vsub(vmul(wc, Br), vmul(ws, Bi));
        u64 wbi = vfma(wc, Bi, vmul(ws, Br));
        // parity sign folded in packed form: sX = sg * X[k], sXm = sg * X[512-k]
        u64 Xkr = vmul(vadd(Ar, wbi), sgv);
        u64 Xki = vmul(vsub(Ai, wbr), sgv);
        u64 Xmr = vmul(vsub(Ar, wbi), sgv);
        u64 Xmi = vmul(vadd(Ai, wbr), ngv);    // sg * (-(Ai+wbr)) = sg * Xmi
        u64 Mk = vfma(Xki, Xki, vmul(Xkr, Xkr));
        u64 Mm = vfma(Xmi, Xmi, vmul(Xmr, Xmr));
        float mk0, mk1, mm0, mm1, kr0, kr1, ki0, ki1, mr0, mr1, mi0, mi1;
        upk(mk0, mk1, Mk); upk(mm0, mm1, Mm);
        upk(kr0, kr1, Xkr); upk(ki0, ki1, Xki);
        upk(mr0, mr1, Xmr); upk(mi0, mi1, Xmi);
        int m = 512 - k;
        if (w0) {
            float rk = fsqrt_fast(mk0), rm = fsqrt_fast(mm0);
            om0[k] = rk; op0[k] = fatan2_half(ki0, kr0, rk);
            om0[m] = rm; op0[m] = fatan2_half(mi0, mr0, rm);
        }
        if (w1) {
            float rk = fsqrt_fast(mk1), rm = fsqrt_fast(mm1);
            om1[k] = rk; op1[k] = fatan2_half(ki1, kr1, rk);
            om1[m] = rm; op1[m] = fatan2_half(mi1, mr1, rm);
        }
    }
    if (tl == 0) {                      // center bin k=256: X = conj(Z256), even parity
        ulonglong2 e = bufA[256];       // 256 ^ ((256>>3)&7) == 256
        float zr0, zr1, zi0, zi1;
        upk(zr0, zr1, e.x); upk(zi0, zi1, e.y);
        if (w0) {
            float r = fsqrt_fast(zr0 * zr0 + zi0 * zi0);
            om0[256] = r; op0[256] = fatan2_half(-zi0, zr0, r);
        }
        if (w1) {
            float r = fsqrt_fast(zr1 * zr1 + zi1 * zi1);
            om1[256] = r; op1[256] = fatan2_half(-zi1, zr1, r);
        }
    }

    // ---- zero-fill rows in [N_FRAMES, N_ROWS) ----
    #pragma unroll
    for (int h = 0; h < 2; h++) {
        int f = f0 + h;
        if (f >= N_FRAMES && f < N_ROWS) {
            float* zm = out + (size_t)f * HALF;
            float* zp = out + (size_t)N_ROWS * HALF + (size_t)f * HALF;
            for (int k = tl; k < HALF; k += 64) { zm[k] = 0.0f; zp[k] = 0.0f; }
        }
    }
}

extern "C" void kernel_launch(void* const* d_in, const int* in_sizes, int n_in,
                              void* d_out, int out_size) {
    const float* x = (const float*)d_in[0];
    float* out = (float*)d_out;
    stft_kernel<<<(N_ROWS + 3) / 4, 128>>>(x, out);
}

// round 16
// speedup vs baseline: 1.6258x; 1.0003x over previous
#include <cuda_runtime.h>

#define SIG_LEN  16777216
#define HOP      256
#define PAD      768
#define N_FRAMES 65539
#define N_ROWS   65542
#define HALF     513

// ---------------- compile-time tables (correctly-rounded, double precision) ----------------
constexpr double PI_D = 3.141592653589793238462643383279502884;

constexpr double tcos(double x) {
    double x2 = x * x, term = 1.0, s = 1.0;
    for (int i = 1; i <= 10; i++) { term *= -x2 / ((2.0 * i - 1.0) * (2.0 * i)); s += term; }
    return s;
}
constexpr double tsin(double x) {
    double x2 = x * x, term = x, s = x;
    for (int i = 1; i <= 10; i++) { term *= -x2 / ((2.0 * i) * (2.0 * i + 1.0)); s += term; }
    return s;
}
constexpr double cpi(double t) {
    while (t >= 2.0) t -= 2.0;
    while (t < 0.0) t += 2.0;
    if (t > 1.0) t = 2.0 - t;
    double sg = 1.0;
    if (t > 0.5) { t = 1.0 - t; sg = -1.0; }
    return sg * (t <= 0.25 ? tcos(PI_D * t) : tsin(PI_D * (0.5 - t)));
}
constexpr double spi(double t) {
    while (t >= 2.0) t -= 2.0;
    while (t < 0.0) t += 2.0;
    double sg = 1.0;
    if (t > 1.0) { t -= 1.0; sg = -1.0; }
    if (t > 0.5) t = 1.0 - t;
    return sg * (t <= 0.25 ? tsin(PI_D * t) : tcos(PI_D * (0.5 - t)));
}

struct Tables {
    float2 tw512[512];    // e^{-2pi i k/512}
    float2 tw64[64];      // {c,s} e^{-2pi i n0 j2/64}
    float2 tw1024[513];   // {c,s} e^{-i pi k/512}
    float2 win[512];      // (w[2n], w[2n+1]) / 32
};
constexpr Tables mk_tables() {
    Tables T{};
    for (int k = 0; k < 512; k++)
        T.tw512[k] = float2{ (float)cpi(k / 256.0), (float)(-spi(k / 256.0)) };
    for (int j2 = 0; j2 < 8; j2++)
        for (int n0 = 0; n0 < 8; n0++)
            T.tw64[j2 * 8 + n0] = float2{ (float)cpi(n0 * j2 / 32.0),
                                          (float)(-spi(n0 * j2 / 32.0)) };
    for (int k = 0; k <= 512; k++)
        T.tw1024[k] = float2{ (float)cpi(k / 512.0), (float)(-spi(k / 512.0)) };
    for (int n = 0; n < 512; n++)
        T.win[n] = float2{ (float)((0.54 - 0.46 * cpi(2.0 * (2 * n) / 1023.0)) / 32.0),
                           (float)((0.54 - 0.46 * cpi(2.0 * (2 * n + 1) / 1023.0)) / 32.0) };
    return T;
}
__device__ constexpr Tables TAB = mk_tables();

// ---------------- f32x2 packed primitives (2 frames in the 2 lanes) ----------------
typedef unsigned long long u64;

__device__ __forceinline__ u64 pk(float lo, float hi) {
    u64 r; asm("mov.b64 %0, {%1, %2};" : "=l"(r) : "f"(lo), "f"(hi)); return r;
}
__device__ __forceinline__ void upk(float& lo, float& hi, u64 v) {
    asm("mov.b64 {%0, %1}, %2;" : "=f"(lo), "=f"(hi) : "l"(v));
}
__device__ __forceinline__ u64 vadd(u64 a, u64 b) {
    u64 r; asm("add.rn.f32x2 %0, %1, %2;" : "=l"(r) : "l"(a), "l"(b)); return r;
}
__device__ __forceinline__ u64 vmul(u64 a, u64 b) {
    u64 r; asm("mul.rn.f32x2 %0, %1, %2;" : "=l"(r) : "l"(a), "l"(b)); return r;
}
__device__ __forceinline__ u64 vfma(u64 a, u64 b, u64 c) {
    u64 r; asm("fma.rn.f32x2 %0, %1, %2, %3;" : "=l"(r) : "l"(a), "l"(b), "l"(c)); return r;
}
__device__ __forceinline__ u64 vneg1() { return pk(-1.0f, -1.0f); }
__device__ __forceinline__ u64 vsub(u64 a, u64 b) { return vfma(b, vneg1(), a); }  // exact a-b

struct cp { u64 re, im; };
__device__ __forceinline__ cp cadd(cp a, cp b)   { return { vadd(a.re, b.re), vadd(a.im, b.im) }; }
__device__ __forceinline__ cp csub(cp a, cp b)   { return { vsub(a.re, b.re), vsub(a.im, b.im) }; }
// a + (-i)b = (are+bim, aim-bre);  a - (-i)b = (are-bim, aim+bre)
__device__ __forceinline__ cp caddmi(cp a, cp b) { return { vadd(a.re, b.im), vsub(a.im, b.re) }; }
__device__ __forceinline__ cp csubmi(cp a, cp b) { return { vsub(a.re, b.im), vadd(a.im, b.re) }; }
__device__ __forceinline__ cp cpmul(cp a, cp b) {
    cp r;
    r.re = vsub(vmul(a.re, b.re), vmul(a.im, b.im));
    r.im = vfma(a.re, b.im, vmul(a.im, b.re));
    return r;
}

__device__ __forceinline__ float fsqrt_fast(float x) {
    float r; asm("sqrt.approx.f32 %0, %1;" : "=f"(r) : "f"(x)); return r;
}

// Half-angle atan2 (scalar) reusing r = |X| (already computed for magnitude).
//   x >= 0: theta = 2*atan(y/(r+|x|));  x < 0: theta = sign(y)*pi - 2*atan(y/(r+|x|))
// 5-coeff odd minimax for atan on [-1,1] (abs err ~1e-5, x2 for half-angle -> ~2e-5 rad;
// budget ~1.45e-3 rad rms). Sign via (y<0) comparison: y==-0.0 & x<0 -> +pi, matching
// the reference at the Nyquist bin (our pair formula makes Im = -0.0 there; rfft has +0).
__device__ __forceinline__ float fatan2_half(float y, float x, float r) {
    const float PI = 3.14159265358979323f;
    float den = r + fabsf(x);
    float t = __fdividef(y, den);
    t = (den == 0.0f) ? 0.0f : t;          // atan2(0,0) = 0
    float s = t * t;
    float p = fmaf(fmaf(fmaf(fmaf(0.0416702f, s, -0.1702660f), s,
                 0.3602820f), s, -0.6605990f), s, 1.9997320f);
    float th = t * p;                       // 2*atan(t)
    if (x < 0.0f) th = ((y < 0.0f) ? -PI : PI) - th;
    return th;
}

// packed 8-point DFT (both frames simultaneously)
__device__ __forceinline__ void fft8p(cp* a) {
    const float Cf = 0.70710678118654752440f;
    u64 Cd = pk(Cf, Cf), nCd = pk(-Cf, -Cf);
    cp s0 = cadd(a[0], a[4]), s1 = csub(a[0], a[4]);
    cp s2 = cadd(a[2], a[6]), s3 = csub(a[2], a[6]);
    cp t0 = cadd(a[1], a[5]), t1 = csub(a[1], a[5]);
    cp t2 = cadd(a[3], a[7]), t3 = csub(a[3], a[7]);
    cp E0 = cadd(s0, s2), E2 = csub(s0, s2);
    cp E1 = caddmi(s1, s3), E3 = csubmi(s1, s3);
    cp O0 = cadd(t0, t2), O2 = csub(t0, t2);
    cp O1 = caddmi(t1, t3), O3 = csubmi(t1, t3);
    cp W1 = { vmul(vadd(O1.re, O1.im), Cd), vmul(vsub(O1.im, O1.re), Cd) };
    cp W3 = { vmul(vsub(O3.im, O3.re), Cd), vmul(vadd(O3.re, O3.im), nCd) };
    a[0] = cadd(E0, O0);   a[4] = csub(E0, O0);
    a[1] = cadd(E1, W1);   a[5] = csub(E1, W1);
    a[2] = caddmi(E2, O2); a[6] = csubmi(E2, O2);   // W2 = -i*O2 folded
    a[3] = cadd(E3, W3);   a[7] = csub(E3, W3);
}

// ---------------- fused STFT kernel: 128 threads, 2 frame-pairs (4 frames)/block ----------
__global__ __launch_bounds__(128, 8) void stft_kernel(const float* __restrict__ x,
                                                      float* __restrict__ out) {
    __shared__ ulonglong2 sA[2][512];

    const int t  = threadIdx.x;
    const int pr = t >> 6;            // frame-pair slot (0-1)
    const int tl = t & 63;
    const int f0 = blockIdx.x * 4 + pr * 2;   // lane .x frame
    const int f1 = f0 + 1;                    // lane .y frame
    const int st0 = f0 * HOP - PAD;
    const int hi = tl >> 3, lo = tl & 7;

    cp v[8];

    // ---- load (batched; frame1 sample n == frame0 sample n+128, index m+2) + window ----
    float2 xs[10];
    const bool inb = (st0 >= 0) && (st0 + 2 * (tl + 64 * 9) + 2 <= SIG_LEN);
    if (inb) {
        #pragma unroll
        for (int m = 0; m < 10; m++)
            xs[m] = *(const float2*)(x + st0 + 2 * (tl + 64 * m));
    } else {
        #pragma unroll
        for (int m = 0; m < 10; m++) {
            int i0 = st0 + 2 * (tl + 64 * m);
            xs[m].x = (i0     >= 0 && i0     < SIG_LEN) ? x[i0]     : 0.0f;
            xs[m].y = (i0 + 1 >= 0 && i0 + 1 < SIG_LEN) ? x[i0 + 1] : 0.0f;
        }
    }
    #pragma unroll
    for (int m = 0; m < 8; m++) {
        float2 w = TAB.win[tl + 64 * m];
        v[m].re = vmul(pk(xs[m].x, xs[m + 2].x), pk(w.x, w.x));
        v[m].im = vmul(pk(xs[m].y, xs[m + 2].y), pk(w.y, w.y));
    }

    // ---- stage 1: fft8 + twiddle powers of tw512[tl] (interleaved: only w1..w4 live) ----
    fft8p(v);
    {
        float2 w1s = TAB.tw512[tl];
        cp w1 = { pk(w1s.x, w1s.x), pk(w1s.y, w1s.y) };
        v[1] = cpmul(v[1], w1);
        cp w2 = cpmul(w1, w1);
        v[2] = cpmul(v[2], w2);
        cp w3 = cpmul(w2, w1);
        v[3] = cpmul(v[3], w3);
        cp w4 = cpmul(w2, w2);
        v[4] = cpmul(v[4], w4);
        v[5] = cpmul(v[5], cpmul(w4, w1));
        v[6] = cpmul(v[6], cpmul(w3, w3));
        v[7] = cpmul(v[7], cpmul(w4, w3));
    }
    ulonglong2* bufA = sA[pr];
    #pragma unroll
    for (int j = 0; j < 8; j++)
        bufA[j * 64 + (((hi ^ j) & 7) << 3) + lo] = make_ulonglong2(v[j].re, v[j].im);
    __syncthreads();

    // ---- stage 2 (read all -> sync -> overwrite same buffer) ----
    #pragma unroll
    for (int m = 0; m < 8; m++) {
        ulonglong2 e = bufA[hi * 64 + (((m ^ hi) & 7) << 3) + lo];
        v[m].re = e.x; v[m].im = e.y;
    }
    fft8p(v);
    #pragma unroll
    for (int j2 = 1; j2 < 8; j2++) {
        float2 wd = TAB.tw64[j2 * 8 + lo];
        cp w = { pk(wd.x, wd.x), pk(wd.y, wd.y) };
        v[j2] = cpmul(v[j2], w);
    }
    __syncthreads();
    #pragma unroll
    for (int j2 = 0; j2 < 8; j2++)
        bufA[j2 * 64 + hi * 8 + (lo ^ j2)] = make_ulonglong2(v[j2].re, v[j2].im);
    __syncthreads();

    // ---- stage 3 ----
    #pragma unroll
    for (int n0 = 0; n0 < 8; n0++) {
        ulonglong2 e = bufA[lo * 64 + hi * 8 + (n0 ^ lo)];
        v[n0].re = e.x; v[n0].im = e.y;
    }
    fft8p(v);
    __syncthreads();
    #pragma unroll
    for (int j3 = 0; j3 < 8; j3++) {
        int k = hi + 8 * lo + 64 * j3;
        bufA[k ^ lo] = make_ulonglong2(v[j3].re, v[j3].im);   // addrR(k)=k^((k>>3)&7)
    }
    __syncthreads();

    // ---- conjugate-pair untangle (packed) + (-1)^k shift (packed) + mag/phase ----
    // Swizzled-index strength reduction (q-invariant XOR operands):
    //   k = tl + 64q (<=255):  swizzle operand = hi        -> kaX = (tl^hi) + 64q
    //   kb = 512-k:            swizzle operand = ((64-tl)>>3)&7 (const over q)
    //                          -> kbX = (64*(7-q) + kbE) & 511,  kbE = (64-tl) ^ op
    //   (&511 also handles the tl=0,q=0 wrap: kb=512 -> Z[0].)
    float* om0 = out + (size_t)f0 * HALF;
    float* op0 = out + (size_t)N_ROWS * HALF + (size_t)f0 * HALF;
    float* om1 = om0 + HALF;
    float* op1 = op0 + HALF;
    const bool w0 = (f0 < N_FRAMES);
    const bool w1 = (f1 < N_FRAMES);
    const u64 Hd = pk(0.5f, 0.5f);

    const int kaB = tl ^ hi;
    const int kbL = 64 - tl;
    const int kbE = kbL ^ ((kbL >> 3) & 7);

    const float sg = (tl & 1) ? -1.0f : 1.0f;   // (-1)^k for k = tl+64q (and 512-k)
    const u64 sgv = pk(sg, sg);
    const u64 ngv = pk(-sg, -sg);
    #pragma unroll
    for (int q = 0; q < 4; q++) {
        int k   = tl + 64 * q;                 // 0..255
        int kaX = kaB + 64 * q;
        int kbX = (64 * (7 - q) + kbE) & 511;
        ulonglong2 ek = bufA[kaX];
        ulonglong2 em = bufA[kbX];
        cp zk = { ek.x, ek.y }, zm = { em.x, em.y };
        u64 Ar = vmul(vadd(zk.re, zm.re), Hd);
        u64 Ai = vmul(vsub(zk.im, zm.im), Hd);
        u64 Br = vmul(vsub(zk.re, zm.re), Hd);
        u64 Bi = vmul(vadd(zk.im, zm.im), Hd);
        float2 wd = TAB.tw1024[k];
        u64 wc = pk(wd.x, wd.x), ws = pk(wd.y, wd.y);
        u64 wbr = vsub(vmul(wc, Br), vmul(ws, Bi));
        u64 wbi = vfma(wc, Bi, vmul(ws, Br));
        // parity sign folded in packed form: sX = sg * X[k], sXm = sg * X[512-k]
        u64 Xkr = vmul(vadd(Ar, wbi), sgv);
        u64 Xki = vmul(vsub(Ai, wbr), sgv);
        u64 Xmr = vmul(vsub(Ar, wbi), sgv);
        u64 Xmi = vmul(vadd(Ai, wbr), ngv);    // sg * (-(Ai+wbr)) = sg * Xmi
        u64 Mk = vfma(Xki, Xki, vmul(Xkr, Xkr));
        u64 Mm = vfma(Xmi, Xmi, vmul(Xmr, Xmr));
        float mk0, mk1, mm0, mm1, kr0, kr1, ki0, ki1, mr0, mr1, mi0, mi1;
        upk(mk0, mk1, Mk); upk(mm0, mm1, Mm);
        upk(kr0, kr1, Xkr); upk(ki0, ki1, Xki);
        upk(mr0, mr1, Xmr); upk(mi0, mi1, Xmi);
        int m = 512 - k;
        if (w0) {
            float rk = fsqrt_fast(mk0), rm = fsqrt_fast(mm0);
            om0[k] = rk; op0[k] = fatan2_half(ki0, kr0, rk);
            om0[m] = rm; op0[m] = fatan2_half(mi0, mr0, rm);
        }
        if (w1) {
            float rk = fsqrt_fast(mk1), rm = fsqrt_fast(mm1);
            om1[k] = rk; op1[k] = fatan2_half(ki1, kr1, rk);
            om1[m] = rm; op1[m] = fatan2_half(mi1, mr1, rm);
        }
    }
    if (tl == 0) {                      // center bin k=256: X = conj(Z256), even parity
        ulonglong2 e = bufA[256];       // 256 ^ ((256>>3)&7) == 256
        float zr0, zr1, zi0, zi1;
        upk(zr0, zr1, e.x); upk(zi0, zi1, e.y);
        if (w0) {
            float r = fsqrt_fast(zr0 * zr0 + zi0 * zi0);
            om0[256] = r; op0[256] = fatan2_half(-zi0, zr0, r);
        }
        if (w1) {
            float r = fsqrt_fast(zr1 * zr1 + zi1 * zi1);
            om1[256] = r; op1[256] = fatan2_half(-zi1, zr1, r);
        }
    }

    // ---- zero-fill rows in [N_FRAMES, N_ROWS) ----
    #pragma unroll
    for (int h = 0; h < 2; h++) {
        int f = f0 + h;
        if (f >= N_FRAMES && f < N_ROWS) {
            float* zm = out + (size_t)f * HALF;
            float* zp = out + (size_t)N_ROWS * HALF + (size_t)f * HALF;
            for (int k = tl; k < HALF; k += 64) { zm[k] = 0.0f; zp[k] = 0.0f; }
        }
    }
}

extern "C" void kernel_launch(void* const* d_in, const int* in_sizes, int n_in,
                              void* d_out, int out_size) {
    const float* x = (const float*)d_in[0];
    float* out = (float*)d_out;
    stft_kernel<<<(N_ROWS + 3) / 4, 128>>>(x, out);
}

// round 17
// speedup vs baseline: 1.6368x; 1.0068x over previous
#include <cuda_runtime.h>

#define SIG_LEN  16777216
#define HOP      256
#define PAD      768
#define N_FRAMES 65539
#define N_ROWS   65542
#define HALF     513

// ---------------- compile-time tables (correctly-rounded, double precision) ----------------
constexpr double PI_D = 3.141592653589793238462643383279502884;

constexpr double tcos(double x) {
    double x2 = x * x, term = 1.0, s = 1.0;
    for (int i = 1; i <= 10; i++) { term *= -x2 / ((2.0 * i - 1.0) * (2.0 * i)); s += term; }
    return s;
}
constexpr double tsin(double x) {
    double x2 = x * x, term = x, s = x;
    for (int i = 1; i <= 10; i++) { term *= -x2 / ((2.0 * i) * (2.0 * i + 1.0)); s += term; }
    return s;
}
constexpr double cpi(double t) {
    while (t >= 2.0) t -= 2.0;
    while (t < 0.0) t += 2.0;
    if (t > 1.0) t = 2.0 - t;
    double sg = 1.0;
    if (t > 0.5) { t = 1.0 - t; sg = -1.0; }
    return sg * (t <= 0.25 ? tcos(PI_D * t) : tsin(PI_D * (0.5 - t)));
}
constexpr double spi(double t) {
    while (t >= 2.0) t -= 2.0;
    while (t < 0.0) t += 2.0;
    double sg = 1.0;
    if (t > 1.0) { t -= 1.0; sg = -1.0; }
    if (t > 0.5) t = 1.0 - t;
    return sg * (t <= 0.25 ? tsin(PI_D * t) : tcos(PI_D * (0.5 - t)));
}

struct Tables {
    float2 tw512[512];    // e^{-2pi i k/512}
    float2 tw64[64];      // {c,s} e^{-2pi i n0 j2/64}
    float2 tw1024[513];   // {c,s} e^{-i pi k/512}
    float2 win[512];      // (w[2n], w[2n+1]) / 32
};
constexpr Tables mk_tables() {
    Tables T{};
    for (int k = 0; k < 512; k++)
        T.tw512[k] = float2{ (float)cpi(k / 256.0), (float)(-spi(k / 256.0)) };
    for (int j2 = 0; j2 < 8; j2++)
        for (int n0 = 0; n0 < 8; n0++)
            T.tw64[j2 * 8 + n0] = float2{ (float)cpi(n0 * j2 / 32.0),
                                          (float)(-spi(n0 * j2 / 32.0)) };
    for (int k = 0; k <= 512; k++)
        T.tw1024[k] = float2{ (float)cpi(k / 512.0), (float)(-spi(k / 512.0)) };
    for (int n = 0; n < 512; n++)
        T.win[n] = float2{ (float)((0.54 - 0.46 * cpi(2.0 * (2 * n) / 1023.0)) / 32.0),
                           (float)((0.54 - 0.46 * cpi(2.0 * (2 * n + 1) / 1023.0)) / 32.0) };
    return T;
}
__device__ constexpr Tables TAB = mk_tables();

// ---------------- f32x2 packed primitives (2 frames in the 2 lanes) ----------------
typedef unsigned long long u64;

__device__ __forceinline__ u64 pk(float lo, float hi) {
    u64 r; asm("mov.b64 %0, {%1, %2};" : "=l"(r) : "f"(lo), "f"(hi)); return r;
}
__device__ __forceinline__ void upk(float& lo, float& hi, u64 v) {
    asm("mov.b64 {%0, %1}, %2;" : "=f"(lo), "=f"(hi) : "l"(v));
}
__device__ __forceinline__ u64 vadd(u64 a, u64 b) {
    u64 r; asm("add.rn.f32x2 %0, %1, %2;" : "=l"(r) : "l"(a), "l"(b)); return r;
}
__device__ __forceinline__ u64 vmul(u64 a, u64 b) {
    u64 r; asm("mul.rn.f32x2 %0, %1, %2;" : "=l"(r) : "l"(a), "l"(b)); return r;
}
__device__ __forceinline__ u64 vfma(u64 a, u64 b, u64 c) {
    u64 r; asm("fma.rn.f32x2 %0, %1, %2, %3;" : "=l"(r) : "l"(a), "l"(b), "l"(c)); return r;
}
__device__ __forceinline__ u64 vneg1() { return pk(-1.0f, -1.0f); }
__device__ __forceinline__ u64 vsub(u64 a, u64 b) { return vfma(b, vneg1(), a); }  // exact a-b

struct cp { u64 re, im; };
__device__ __forceinline__ cp cadd(cp a, cp b)   { return { vadd(a.re, b.re), vadd(a.im, b.im) }; }
__device__ __forceinline__ cp csub(cp a, cp b)   { return { vsub(a.re, b.re), vsub(a.im, b.im) }; }
// a + (-i)b = (are+bim, aim-bre);  a - (-i)b = (are-bim, aim+bre)
__device__ __forceinline__ cp caddmi(cp a, cp b) { return { vadd(a.re, b.im), vsub(a.im, b.re) }; }
__device__ __forceinline__ cp csubmi(cp a, cp b) { return { vsub(a.re, b.im), vadd(a.im, b.re) }; }
__device__ __forceinline__ cp cpmul(cp a, cp b) {
    cp r;
    r.re = vsub(vmul(a.re, b.re), vmul(a.im, b.im));
    r.im = vfma(a.re, b.im, vmul(a.im, b.re));
    return r;
}

__device__ __forceinline__ float fsqrt_fast(float x) {
    float r; asm("sqrt.approx.f32 %0, %1;" : "=f"(r) : "f"(x)); return r;
}

// Half-angle atan2 (scalar) reusing r = |X| (already computed for magnitude).
//   x >= 0: theta = 2*atan(y/(r+|x|));  x < 0: theta = sign(y)*pi - 2*atan(y/(r+|x|))
// 5-coeff odd minimax for atan on [-1,1] (abs err ~1e-5, x2 for half-angle -> ~2e-5 rad;
// budget ~1.45e-3 rad rms). Sign via (y<0) comparison: y==-0.0 & x<0 -> +pi, matching
// the reference at the Nyquist bin (our pair formula makes Im = -0.0 there; rfft has +0).
__device__ __forceinline__ float fatan2_half(float y, float x, float r) {
    const float PI = 3.14159265358979323f;
    float den = r + fabsf(x);
    float t = __fdividef(y, den);
    t = (den == 0.0f) ? 0.0f : t;          // atan2(0,0) = 0
    float s = t * t;
    float p = fmaf(fmaf(fmaf(fmaf(0.0416702f, s, -0.1702660f), s,
                 0.3602820f), s, -0.6605990f), s, 1.9997320f);
    float th = t * p;                       // 2*atan(t)
    if (x < 0.0f) th = ((y < 0.0f) ? -PI : PI) - th;
    return th;
}

// packed 8-point DFT (both frames simultaneously)
__device__ __forceinline__ void fft8p(cp* a) {
    const float Cf = 0.70710678118654752440f;
    u64 Cd = pk(Cf, Cf), nCd = pk(-Cf, -Cf);
    cp s0 = cadd(a[0], a[4]), s1 = csub(a[0], a[4]);
    cp s2 = cadd(a[2], a[6]), s3 = csub(a[2], a[6]);
    cp t0 = cadd(a[1], a[5]), t1 = csub(a[1], a[5]);
    cp t2 = cadd(a[3], a[7]), t3 = csub(a[3], a[7]);
    cp E0 = cadd(s0, s2), E2 = csub(s0, s2);
    cp E1 = caddmi(s1, s3), E3 = csubmi(s1, s3);
    cp O0 = cadd(t0, t2), O2 = csub(t0, t2);
    cp O1 = caddmi(t1, t3), O3 = csubmi(t1, t3);
    cp W1 = { vmul(vadd(O1.re, O1.im), Cd), vmul(vsub(O1.im, O1.re), Cd) };
    cp W3 = { vmul(vsub(O3.im, O3.re), Cd), vmul(vadd(O3.re, O3.im), nCd) };
    a[0] = cadd(E0, O0);   a[4] = csub(E0, O0);
    a[1] = cadd(E1, W1);   a[5] = csub(E1, W1);
    a[2] = caddmi(E2, O2); a[6] = csubmi(E2, O2);   // W2 = -i*O2 folded
    a[3] = cadd(E3, W3);   a[7] = csub(E3, W3);
}

// ---------------- fused STFT kernel: 64 threads = ONE frame-pair per block ----------------
// Same math/memory patterns as the 128-thread version; smaller blocks decouple
// frame-pairs (2-warp barriers, independent retirement, finer scheduling).
__global__ __launch_bounds__(64, 16) void stft_kernel(const float* __restrict__ x,
                                                      float* __restrict__ out) {
    __shared__ ulonglong2 bufA[512];

    const int tl = threadIdx.x;               // 0..63
    const int f0 = blockIdx.x * 2;            // lane .x frame
    const int f1 = f0 + 1;                    // lane .y frame
    const int st0 = f0 * HOP - PAD;
    const int hi = tl >> 3, lo = tl & 7;

    cp v[8];

    // ---- load (batched; frame1 sample n == frame0 sample n+128, index m+2) + window ----
    float2 xs[10];
    const bool inb = (st0 >= 0) && (st0 + 2 * (tl + 64 * 9) + 2 <= SIG_LEN);
    if (inb) {
        #pragma unroll
        for (int m = 0; m < 10; m++)
            xs[m] = *(const float2*)(x + st0 + 2 * (tl + 64 * m));
    } else {
        #pragma unroll
        for (int m = 0; m < 10; m++) {
            int i0 = st0 + 2 * (tl + 64 * m);
            xs[m].x = (i0     >= 0 && i0     < SIG_LEN) ? x[i0]     : 0.0f;
            xs[m].y = (i0 + 1 >= 0 && i0 + 1 < SIG_LEN) ? x[i0 + 1] : 0.0f;
        }
    }
    #pragma unroll
    for (int m = 0; m < 8; m++) {
        float2 w = TAB.win[tl + 64 * m];
        v[m].re = vmul(pk(xs[m].x, xs[m + 2].x), pk(w.x, w.x));
        v[m].im = vmul(pk(xs[m].y, xs[m + 2].y), pk(w.y, w.y));
    }

    // ---- stage 1: fft8 + twiddle powers of tw512[tl] (interleaved: only w1..w4 live) ----
    fft8p(v);
    {
        float2 w1s = TAB.tw512[tl];
        cp w1 = { pk(w1s.x, w1s.x), pk(w1s.y, w1s.y) };
        v[1] = cpmul(v[1], w1);
        cp w2 = cpmul(w1, w1);
        v[2] = cpmul(v[2], w2);
        cp w3 = cpmul(w2, w1);
        v[3] = cpmul(v[3], w3);
        cp w4 = cpmul(w2, w2);
        v[4] = cpmul(v[4], w4);
        v[5] = cpmul(v[5], cpmul(w4, w1));
        v[6] = cpmul(v[6], cpmul(w3, w3));
        v[7] = cpmul(v[7], cpmul(w4, w3));
    }
    #pragma unroll
    for (int j = 0; j < 8; j++)
        bufA[j * 64 + (((hi ^ j) & 7) << 3) + lo] = make_ulonglong2(v[j].re, v[j].im);
    __syncthreads();

    // ---- stage 2 (read all -> sync -> overwrite same buffer) ----
    #pragma unroll
    for (int m = 0; m < 8; m++) {
        ulonglong2 e = bufA[hi * 64 + (((m ^ hi) & 7) << 3) + lo];
        v[m].re = e.x; v[m].im = e.y;
    }
    fft8p(v);
    #pragma unroll
    for (int j2 = 1; j2 < 8; j2++) {
        float2 wd = TAB.tw64[j2 * 8 + lo];
        cp w = { pk(wd.x, wd.x), pk(wd.y, wd.y) };
        v[j2] = cpmul(v[j2], w);
    }
    __syncthreads();
    #pragma unroll
    for (int j2 = 0; j2 < 8; j2++)
        bufA[j2 * 64 + hi * 8 + (lo ^ j2)] = make_ulonglong2(v[j2].re, v[j2].im);
    __syncthreads();

    // ---- stage 3 ----
    #pragma unroll
    for (int n0 = 0; n0 < 8; n0++) {
        ulonglong2 e = bufA[lo * 64 + hi * 8 + (n0 ^ lo)];
        v[n0].re = e.x; v[n0].im = e.y;
    }
    fft8p(v);
    __syncthreads();
    #pragma unroll
    for (int j3 = 0; j3 < 8; j3++) {
        int k = hi + 8 * lo + 64 * j3;
        bufA[k ^ lo] = make_ulonglong2(v[j3].re, v[j3].im);   // addrR(k)=k^((k>>3)&7)
    }
    __syncthreads();

    // ---- conjugate-pair untangle (packed) + (-1)^k shift (packed) + mag/phase ----
    // Swizzled-index strength reduction (q-invariant XOR operands):
    //   k = tl + 64q (<=255):  swizzle operand = hi        -> kaX = (tl^hi) + 64q
    //   kb = 512-k:            swizzle operand = ((64-tl)>>3)&7 (const over q)
    //                          -> kbX = (64*(7-q) + kbE) & 511,  kbE = (64-tl) ^ op
    //   (&511 also handles the tl=0,q=0 wrap: kb=512 -> Z[0].)
    float* om0 = out + (size_t)f0 * HALF;
    float* op0 = out + (size_t)N_ROWS * HALF + (size_t)f0 * HALF;
    float* om1 = om0 + HALF;
    float* op1 = op0 + HALF;
    const bool w0 = (f0 < N_FRAMES);
    const bool w1 = (f1 < N_FRAMES);
    const u64 Hd = pk(0.5f, 0.5f);

    const int kaB = tl ^ hi;
    const int kbL = 64 - tl;
    const int kbE = kbL ^ ((kbL >> 3) & 7);

    const float sg = (tl & 1) ? -1.0f : 1.0f;   // (-1)^k for k = tl+64q (and 512-k)
    const u64 sgv = pk(sg, sg);
    const u64 ngv = pk(-sg, -sg);
    #pragma unroll
    for (int q = 0; q < 4; q++) {
        int k   = tl + 64 * q;                 // 0..255
        int kaX = kaB + 64 * q;
        int kbX = (64 * (7 - q) + kbE) & 511;
        ulonglong2 ek = bufA[kaX];
        ulonglong2 em = bufA[kbX];
        cp zk = { ek.x, ek.y }, zm = { em.x, em.y };
        u64 Ar = vmul(vadd(zk.re, zm.re), Hd);
        u64 Ai = vmul(vsub(zk.im, zm.im), Hd);
        u64 Br = vmul(vsub(zk.re, zm.re), Hd);
        u64 Bi = vmul(vadd(zk.im, zm.im), Hd);
        float2 wd = TAB.tw1024[k];
        u64 wc = pk(wd.x, wd.x), ws = pk(wd.y, wd.y);
        u64 wbr = vsub(vmul(wc, Br), vmul(ws, Bi));
        u64 wbi = vfma(wc, Bi, vmul(ws, Br));
        // parity sign folded in packed form: sX = sg * X[k], sXm = sg * X[512-k]
        u64 Xkr = vmul(vadd(Ar, wbi), sgv);
        u64 Xki = vmul(vsub(Ai, wbr), sgv);
        u64 Xmr = vmul(vsub(Ar, wbi), sgv);
        u64 Xmi = vmul(vadd(Ai, wbr), ngv);    // sg * (-(Ai+wbr)) = sg * Xmi
        u64 Mk = vfma(Xki, Xki, vmul(Xkr, Xkr));
        u64 Mm = vfma(Xmi, Xmi, vmul(Xmr, Xmr));
        float mk0, mk1, mm0, mm1, kr0, kr1, ki0, ki1, mr0, mr1, mi0, mi1;
        upk(mk0, mk1, Mk); upk(mm0, mm1, Mm);
        upk(kr0, kr1, Xkr); upk(ki0, ki1, Xki);
        upk(mr0, mr1, Xmr); upk(mi0, mi1, Xmi);
        int m = 512 - k;
        if (w0) {
            float rk = fsqrt_fast(mk0), rm = fsqrt_fast(mm0);
            om0[k] = rk; op0[k] = fatan2_half(ki0, kr0, rk);
            om0[m] = rm; op0[m] = fatan2_half(mi0, mr0, rm);
        }
        if (w1) {
            float rk = fsqrt_fast(mk1), rm = fsqrt_fast(mm1);
            om1[k] = rk; op1[k] = fatan2_half(ki1, kr1, rk);
            om1[m] = rm; op1[m] = fatan2_half(mi1, mr1, rm);
        }
    }
    if (tl == 0) {                      // center bin k=256: X = conj(Z256), even parity
        ulonglong2 e = bufA[256];       // 256 ^ ((256>>3)&7) == 256
        float zr0, zr1, zi0, zi1;
        upk(zr0, zr1, e.x); upk(zi0, zi1, e.y);
        if (w0) {
            float r = fsqrt_fast(zr0 * zr0 + zi0 * zi0);
            om0[256] = r; op0[256] = fatan2_half(-zi0, zr0, r);
        }
        if (w1) {
            float r = fsqrt_fast(zr1 * zr1 + zi1 * zi1);
            om1[256] = r; op1[256] = fatan2_half(-zi1, zr1, r);
        }
    }

    // ---- zero-fill rows in [N_FRAMES, N_ROWS) ----
    #pragma unroll
    for (int h = 0; h < 2; h++) {
        int f = f0 + h;
        if (f >= N_FRAMES && f < N_ROWS) {
            float* zm = out + (size_t)f * HALF;
            float* zp = out + (size_t)N_ROWS * HALF + (size_t)f * HALF;
            for (int k = tl; k < HALF; k += 64) { zm[k] = 0.0f; zp[k] = 0.0f; }
        }
    }
}

extern "C" void kernel_launch(void* const* d_in, const int* in_sizes, int n_in,
                              void* d_out, int out_size) {
    const float* x = (const float*)d_in[0];
    float* out = (float*)d_out;
    stft_kernel<<<(N_ROWS + 1) / 2, 64>>>(x, out);
}